// round 5
// baseline (speedup 1.0000x reference)
#include <cuda_runtime.h>
#include <cstdint>

typedef unsigned long long ull;

// Problem constants (fixed shapes for this dataset)
constexpr int NN = 100000;   // nodes
constexpr int EE = 1600000;  // edges (without self loops)
constexpr int SCAN_NBLK = (NN + 1023) / 1024;  // 98

struct __align__(8) Edge { int s; float w; };

// ---------------- static device scratch (no allocation allowed) --------------
__device__ int   g_is64;             // 1 if edge_index is int64, 0 if int32
__device__ int   g_cnt[NN];          // in-degree counts, later reused as cursor
__device__ int   g_rowptr[NN + 1];   // CSR row pointers (by dst)
__device__ int   g_bsum[128];        // scan block sums
__device__ float g_dinv[NN];         // deg^-1/2
__device__ Edge  g_edge[EE];         // CSR: (src, norm) per edge
__device__ float g_buf1[(size_t)NN * 128];
__device__ float g_buf2[(size_t)NN * 128];

// Resolve buffer selector in DEVICE code.
__device__ __forceinline__ const float* sel_src(const float* ext, int s) {
    return s == 0 ? ext : (s == 1 ? (const float*)g_buf1 : (const float*)g_buf2);
}
__device__ __forceinline__ float* sel_dst(float* ext, int s) {
    return s == 0 ? ext : (s == 1 ? (float*)g_buf1 : (float*)g_buf2);
}

// packed fp32x2 FMA: d = a*b + d   (FFMA2 in SASS; PTX ISA 8.6, sm_100+)
__device__ __forceinline__ void fma2(ull& d, ull a, ull b) {
    asm("fma.rn.f32x2 %0, %1, %2, %0;" : "+l"(d) : "l"(a), "l"(b));
}
__device__ __forceinline__ float lo32(ull p) { return __uint_as_float((unsigned)p); }
__device__ __forceinline__ float hi32(ull p) { return __uint_as_float((unsigned)(p >> 32)); }

// ---------------- init: zero counts; block 0 warp 0 detects dtype ------------
// int64 entries (values < 2^31, nonneg) have zero high words at odd 32-bit
// positions; int32 data has random indices there.
__global__ void k_init(const int* __restrict__ w) {
    int i = blockIdx.x * blockDim.x + threadIdx.x;
    if (i < NN) g_cnt[i] = 0;
    if (blockIdx.x == 0 && threadIdx.x < 32) {
        int lane = threadIdx.x;
        int acc = 0;
        for (int j = lane; j < 1024; j += 32) acc |= w[2 * j + 1];
#pragma unroll
        for (int off = 16; off > 0; off >>= 1)
            acc |= __shfl_xor_sync(0xffffffffu, acc, off);
        if (lane == 0) g_is64 = (acc == 0) ? 1 : 0;
    }
}

__device__ __forceinline__ int load_idx(const int* __restrict__ w, int pos, int is64) {
    if (is64) return ((const int2*)w)[pos].x;  // low word == value (<2^31, nonneg)
    return w[pos];
}

__global__ void k_count(const int* __restrict__ w, int E) {
    int e = blockIdx.x * blockDim.x + threadIdx.x;
    if (e < E) {
        int is64 = g_is64;
        int d = load_idx(w, E + e, is64);  // dst row
        if ((unsigned)d < (unsigned)NN) atomicAdd(&g_cnt[d], 1);
    }
}

// scan pass 1: per-block (1024 elems) total -> g_bsum; also computes dinv
__global__ void k_scan1() {
    __shared__ int s[256];
    int b = blockIdx.x, tid = threadIdx.x;
    int base = b * 1024 + tid * 4;
    int local = 0;
#pragma unroll
    for (int j = 0; j < 4; j++) {
        int i = base + j;
        if (i < NN) {
            int c = g_cnt[i];
            local += c;
            g_dinv[i] = rsqrtf((float)(c + 1));  // +1 self loop
        }
    }
    s[tid] = local;
    __syncthreads();
    for (int off = 128; off > 0; off >>= 1) {
        if (tid < off) s[tid] += s[tid + off];
        __syncthreads();
    }
    if (tid == 0) g_bsum[b] = s[0];
}

// scan pass 2: exclusive scan of block sums (single block)
__global__ void k_scan2() {
    __shared__ int s[128];
    int tid = threadIdx.x;
    int v = (tid < SCAN_NBLK) ? g_bsum[tid] : 0;
    s[tid] = v;
    __syncthreads();
    for (int off = 1; off < 128; off <<= 1) {
        int t = (tid >= off) ? s[tid - off] : 0;
        __syncthreads();
        s[tid] += t;
        __syncthreads();
    }
    if (tid < SCAN_NBLK) g_bsum[tid] = s[tid] - v;  // exclusive
    if (tid == 127) g_rowptr[NN] = s[127];          // total
}

// scan pass 3: write rowptr AND cursor copy (g_cnt)
__global__ void k_scan3() {
    __shared__ int s[256];
    int b = blockIdx.x, tid = threadIdx.x;
    int base = b * 1024 + tid * 4;
    int v[4];
#pragma unroll
    for (int j = 0; j < 4; j++) {
        int i = base + j;
        v[j] = (i < NN) ? g_cnt[i] : 0;
    }
    int local = v[0] + v[1] + v[2] + v[3];
    s[tid] = local;
    __syncthreads();
    for (int off = 1; off < 256; off <<= 1) {
        int t = (tid >= off) ? s[tid - off] : 0;
        __syncthreads();
        s[tid] += t;
        __syncthreads();
    }
    int excl = s[tid] - local + g_bsum[b];
#pragma unroll
    for (int j = 0; j < 4; j++) {
        int i = base + j;
        if (i < NN) { g_rowptr[i] = excl; g_cnt[i] = excl; }
        excl += v[j];
    }
}

__global__ void k_scatter(const int* __restrict__ w, int E) {
    int e = blockIdx.x * blockDim.x + threadIdx.x;
    if (e < E) {
        int is64 = g_is64;
        int s = load_idx(w, e, is64);
        int d = load_idx(w, E + e, is64);
        if ((unsigned)s < (unsigned)NN && (unsigned)d < (unsigned)NN) {
            int pos = atomicAdd(&g_cnt[d], 1);
            Edge ed; ed.s = s; ed.w = g_dinv[s] * g_dinv[d];
            g_edge[pos] = ed;  // single ST.64
        }
    }
}

// ---------------- aggregation: GRP lanes per node, VEC floats per lane -------
// out[i] = dinv[i]^2 * h[i] + sum_e w_e * h[src_e]   (+bias, relu optional)
template <int CH, int GRP, int VEC, bool BIAS, bool RELU>
__global__ void k_agg(const float* __restrict__ hext, int hs,
                      float* __restrict__ oext, int ds,
                      const float* __restrict__ bias) {
    const float* __restrict__ h = sel_src(hext, hs);
    float* __restrict__ out = sel_dst(oext, ds);
    int node = (blockIdx.x * blockDim.x + threadIdx.x) / GRP;
    int sub  = threadIdx.x % GRP;
    if (node >= NN) return;
    constexpr int NV = CH / VEC;            // active sublanes
    bool act = (NV == GRP) || (sub < NV);
    int c0 = sub * VEC;

    float acc[VEC];
#pragma unroll
    for (int v = 0; v < VEC; v++) acc[v] = 0.f;

    float sd = g_dinv[node];
    sd *= sd;
    if (act) {
        const float* hr = h + (size_t)node * CH + c0;
#pragma unroll
        for (int v = 0; v < VEC; v++) acc[v] = sd * hr[v];
    }

    int e = g_rowptr[node], end = g_rowptr[node + 1];
#pragma unroll 2
    for (; e < end; e++) {
        Edge ed = g_edge[e];  // broadcast LDG.64
        const float* hr = h + (size_t)ed.s * CH + c0;
        if (act) {
            if (VEC == 4) {
                float4 v4 = *(const float4*)hr;
                acc[0] += ed.w * v4.x; acc[1] += ed.w * v4.y;
                acc[2] += ed.w * v4.z; acc[3] += ed.w * v4.w;
            } else if (VEC == 2) {
                float2 v2 = *(const float2*)hr;
                acc[0] += ed.w * v2.x; acc[1] += ed.w * v2.y;
            } else {
                acc[0] += ed.w * hr[0];
            }
        }
    }

    if (act) {
        float* orow = out + (size_t)node * CH + c0;
#pragma unroll
        for (int v = 0; v < VEC; v++) {
            float t = acc[v];
            if (BIAS) t += bias[c0 + v];
            if (RELU) t = fmaxf(t, 0.f);
            acc[v] = t;
        }
        if (VEC == 4)      *(float4*)orow = make_float4(acc[0], acc[1], acc[2], acc[3]);
        else if (VEC == 2) *(float2*)orow = make_float2(acc[0], acc[1]);
        else               orow[0] = acc[0];
    }
}

// ---------------- dense GEMM via packed FFMA2 --------------------------------
// out = h @ W (+b, relu). BN=64 nodes/block, 8x8 per thread via fp32x2 pairs.
// H staged DUPLICATED in smem -> (h,h) splat pairs load straight as b64 regs.
// W staged naturally -> (w_c, w_c+1) channel pairs. Zero pack instructions.
template <int IN, int OUT, int KC, bool BIAS, bool RELU>
__global__ void k_gemm(const float* __restrict__ hext, int hs,
                       const float* __restrict__ W,
                       const float* __restrict__ b,
                       float* __restrict__ oext, int ds) {
    const float* __restrict__ h = sel_src(hext, hs);
    float* __restrict__ out = sel_dst(oext, ds);
    constexpr int BN = 64;
    constexpr int H2 = 2 * BN + 8;   // duplicated row stride (floats), 16B-mult
    constexpr int TX = OUT / 8;
    constexpr int NT = TX * 8;
    __shared__ float Wsm[KC * OUT];
    __shared__ float Hsm[KC * H2];

    int tx = threadIdx.x, ty = threadIdx.y;
    int tid = ty * TX + tx;
    int n0blk = blockIdx.x * BN;

    ull acc[8][4];
#pragma unroll
    for (int a = 0; a < 8; a++)
#pragma unroll
        for (int c = 0; c < 4; c++) acc[a][c] = 0ull;

    for (int kc0 = 0; kc0 < IN; kc0 += KC) {
        for (int i = tid; i < KC * OUT; i += NT) Wsm[i] = W[kc0 * OUT + i];
        for (int i = tid; i < BN * KC; i += NT) {
            int n = i / KC, k = i - n * KC;
            int node = n0blk + n;
            float v = (node < NN) ? h[(size_t)node * IN + kc0 + k] : 0.f;
            Hsm[k * H2 + 2 * n] = v;
            Hsm[k * H2 + 2 * n + 1] = v;
        }
        __syncthreads();

#pragma unroll 4
        for (int k = 0; k < KC; k++) {
            // H splats: nodes {4ty..4ty+3} and {32+4ty..+3}, each ull = (h,h)
            const ulonglong2* hp = (const ulonglong2*)&Hsm[k * H2];
            ulonglong2 hA = hp[2 * ty];       // nodes 4ty, 4ty+1
            ulonglong2 hB = hp[2 * ty + 1];   // nodes 4ty+2, 4ty+3
            ulonglong2 hC = hp[16 + 2 * ty];  // nodes 32+4ty, 32+4ty+1
            ulonglong2 hD = hp[17 + 2 * ty];  // nodes 32+4ty+2, +3
            ull hv[8] = {hA.x, hA.y, hB.x, hB.y, hC.x, hC.y, hD.x, hD.y};
            // W channel pairs: {4tx..+3} and {OUT/2+4tx..+3}
            const ulonglong2* wp = (const ulonglong2*)&Wsm[k * OUT];
            ulonglong2 wA = wp[tx];            // (c0,c0+1),(c0+2,c0+3)
            ulonglong2 wB = wp[OUT / 8 + tx];  // second half channels
            ull wv[4] = {wA.x, wA.y, wB.x, wB.y};
#pragma unroll
            for (int a = 0; a < 8; a++)
#pragma unroll
                for (int c = 0; c < 4; c++) fma2(acc[a][c], hv[a], wv[c]);
        }
        __syncthreads();
    }

    // epilogue
    int cA = tx * 4, cB = OUT / 2 + tx * 4;
    float4 bA = make_float4(0.f, 0.f, 0.f, 0.f), bB = bA;
    if (BIAS) {
        bA = *(const float4*)&b[cA];
        bB = *(const float4*)&b[cB];
    }
#pragma unroll
    for (int a = 0; a < 8; a++) {
        int node = n0blk + ((a < 4) ? (ty * 4 + a) : (32 + ty * 4 + a - 4));
        if (node < NN) {
            float4 oA = make_float4(lo32(acc[a][0]) + bA.x, hi32(acc[a][0]) + bA.y,
                                    lo32(acc[a][1]) + bA.z, hi32(acc[a][1]) + bA.w);
            float4 oB = make_float4(lo32(acc[a][2]) + bB.x, hi32(acc[a][2]) + bB.y,
                                    lo32(acc[a][3]) + bB.z, hi32(acc[a][3]) + bB.w);
            if (RELU) {
                oA.x = fmaxf(oA.x, 0.f); oA.y = fmaxf(oA.y, 0.f);
                oA.z = fmaxf(oA.z, 0.f); oA.w = fmaxf(oA.w, 0.f);
                oB.x = fmaxf(oB.x, 0.f); oB.y = fmaxf(oB.y, 0.f);
                oB.z = fmaxf(oB.z, 0.f); oB.w = fmaxf(oB.w, 0.f);
            }
            *(float4*)&out[(size_t)node * OUT + cA] = oA;
            *(float4*)&out[(size_t)node * OUT + cB] = oB;
        }
    }
}

// ---------------- launch ------------------------------------------------------
extern "C" void kernel_launch(void* const* d_in, const int* in_sizes, int n_in,
                              void* d_out, int out_size) {
    const float* x  = (const float*)d_in[0];
    const int* ei32 = (const int*)d_in[1];   // edge_index words (int32 or int64)
    const float* W1 = (const float*)d_in[2];
    const float* b1 = (const float*)d_in[3];
    const float* W2 = (const float*)d_in[4];
    const float* b2 = (const float*)d_in[5];
    const float* W3 = (const float*)d_in[6];
    const float* b3 = (const float*)d_in[7];
    float* out      = (float*)d_out;
    int E = in_sizes[1] / 2;  // element count is 2E for both int32 and int64

    // --- dtype detect + CSR build (5 kernels) ---
    k_init<<<(NN + 255) / 256, 256>>>(ei32);
    k_count<<<(E + 255) / 256, 256>>>(ei32, E);
    k_scan1<<<SCAN_NBLK, 256>>>();
    k_scan2<<<1, 128>>>();
    k_scan3<<<SCAN_NBLK, 256>>>();
    k_scatter<<<(E + 255) / 256, 256>>>(ei32, E);

    int aggW = (NN * 32 + 255) / 256;   // GRP=32
    int aggH = (NN * 16 + 255) / 256;   // GRP=16
    int gB = (NN + 63) / 64;            // GEMM blocks (BN=64)

    // layer 1: agg(x)[12] -> GEMM 12->64 (+b1, relu)   x -> buf1 -> buf2
    k_agg<12, 16, 1, false, false><<<aggH, 256>>>(x, 0, nullptr, 1, nullptr);
    k_gemm<12, 64, 12, true, true><<<gB, dim3(8, 8)>>>(nullptr, 1, W1, b1, nullptr, 2);

    // layer 2: agg(h1)[64] -> GEMM 64->128 (+b2, relu)   buf2 -> buf1 -> buf2
    k_agg<64, 32, 2, false, false><<<aggW, 256>>>(nullptr, 2, nullptr, 1, nullptr);
    k_gemm<64, 128, 32, true, true><<<gB, dim3(16, 8)>>>(nullptr, 1, W2, b2, nullptr, 2);

    // layer 3: GEMM 128->96 (no bias) -> agg[96] (+b3)   buf2 -> buf1 -> out
    k_gemm<128, 96, 32, false, false><<<gB, dim3(12, 8)>>>(nullptr, 2, W3, nullptr, nullptr, 1);
    k_agg<96, 32, 4, true, false><<<aggW, 256>>>(nullptr, 1, out, 0, b3);
}

// round 7
// speedup vs baseline: 1.3071x; 1.3071x over previous
#include <cuda_runtime.h>
#include <cstdint>

typedef unsigned long long ull;

constexpr int NN = 100000;   // nodes
constexpr int EE = 1600000;  // edges (no self loops)
constexpr int SCAN_NBLK = (NN + 1023) / 1024;  // 98

struct __align__(8) Edge { int s; float w; };

// ---------------- static device scratch --------------------------------------
__device__ int   g_is64;
__device__ int   g_cnt[NN];
__device__ int   g_rowptr[NN + 1];
__device__ int   g_bsum[128];
__device__ float g_dinv[NN];
__device__ Edge  g_edge[EE];
__device__ float g_buf1[(size_t)NN * 128];
__device__ float g_buf2[(size_t)NN * 128];

__device__ __forceinline__ const float* sel_src(const float* ext, int s) {
    return s == 0 ? ext : (s == 1 ? (const float*)g_buf1 : (const float*)g_buf2);
}
__device__ __forceinline__ float* sel_dst(float* ext, int s) {
    return s == 0 ? ext : (s == 1 ? (float*)g_buf1 : (float*)g_buf2);
}

// tf32 helpers (arch-agnostic PTX, sm_80+)
__device__ __forceinline__ uint32_t f2tf32(float f) {
    uint32_t r;
    asm("cvt.rna.tf32.f32 %0, %1;" : "=r"(r) : "f"(f));
    return r;
}
__device__ __forceinline__ void mma_tf32_16n8k8(float* c, const uint32_t* a,
                                                const uint32_t* b) {
    asm volatile(
        "mma.sync.aligned.m16n8k8.row.col.f32.tf32.tf32.f32 "
        "{%0,%1,%2,%3}, {%4,%5,%6,%7}, {%8,%9}, {%0,%1,%2,%3};"
        : "+f"(c[0]), "+f"(c[1]), "+f"(c[2]), "+f"(c[3])
        : "r"(a[0]), "r"(a[1]), "r"(a[2]), "r"(a[3]), "r"(b[0]), "r"(b[1]));
}

// ---------------- init + dtype detect ----------------------------------------
// int64 entries (<2^31, nonneg) have zero high words at odd 32-bit positions.
__global__ void k_init(const int* __restrict__ w) {
    int i = blockIdx.x * blockDim.x + threadIdx.x;
    if (i < NN) g_cnt[i] = 0;
    if (blockIdx.x == 0 && threadIdx.x < 32) {
        int lane = threadIdx.x;
        int acc = 0;
        for (int j = lane; j < 1024; j += 32) acc |= w[2 * j + 1];
#pragma unroll
        for (int off = 16; off > 0; off >>= 1)
            acc |= __shfl_xor_sync(0xffffffffu, acc, off);
        if (lane == 0) g_is64 = (acc == 0) ? 1 : 0;
    }
}

__device__ __forceinline__ int load_idx(const int* __restrict__ w, int pos, int is64) {
    if (is64) return ((const int2*)w)[pos].x;
    return w[pos];
}

__global__ void k_count(const int* __restrict__ w, int E) {
    int e = blockIdx.x * blockDim.x + threadIdx.x;
    if (e < E) {
        int is64 = g_is64;
        int d = load_idx(w, E + e, is64);
        if ((unsigned)d < (unsigned)NN) atomicAdd(&g_cnt[d], 1);
    }
}

__global__ void k_scan1() {
    __shared__ int s[256];
    int b = blockIdx.x, tid = threadIdx.x;
    int base = b * 1024 + tid * 4;
    int local = 0;
#pragma unroll
    for (int j = 0; j < 4; j++) {
        int i = base + j;
        if (i < NN) {
            int c = g_cnt[i];
            local += c;
            g_dinv[i] = rsqrtf((float)(c + 1));
        }
    }
    s[tid] = local;
    __syncthreads();
    for (int off = 128; off > 0; off >>= 1) {
        if (tid < off) s[tid] += s[tid + off];
        __syncthreads();
    }
    if (tid == 0) g_bsum[b] = s[0];
}

__global__ void k_scan2() {
    __shared__ int s[128];
    int tid = threadIdx.x;
    int v = (tid < SCAN_NBLK) ? g_bsum[tid] : 0;
    s[tid] = v;
    __syncthreads();
    for (int off = 1; off < 128; off <<= 1) {
        int t = (tid >= off) ? s[tid - off] : 0;
        __syncthreads();
        s[tid] += t;
        __syncthreads();
    }
    if (tid < SCAN_NBLK) g_bsum[tid] = s[tid] - v;
    if (tid == 127) g_rowptr[NN] = s[127];
}

__global__ void k_scan3() {
    __shared__ int s[256];
    int b = blockIdx.x, tid = threadIdx.x;
    int base = b * 1024 + tid * 4;
    int v[4];
#pragma unroll
    for (int j = 0; j < 4; j++) {
        int i = base + j;
        v[j] = (i < NN) ? g_cnt[i] : 0;
    }
    int local = v[0] + v[1] + v[2] + v[3];
    s[tid] = local;
    __syncthreads();
    for (int off = 1; off < 256; off <<= 1) {
        int t = (tid >= off) ? s[tid - off] : 0;
        __syncthreads();
        s[tid] += t;
        __syncthreads();
    }
    int excl = s[tid] - local + g_bsum[b];
#pragma unroll
    for (int j = 0; j < 4; j++) {
        int i = base + j;
        if (i < NN) { g_rowptr[i] = excl; g_cnt[i] = excl; }
        excl += v[j];
    }
}

__global__ void k_scatter(const int* __restrict__ w, int E) {
    int e = blockIdx.x * blockDim.x + threadIdx.x;
    if (e < E) {
        int is64 = g_is64;
        int s = load_idx(w, e, is64);
        int d = load_idx(w, E + e, is64);
        if ((unsigned)s < (unsigned)NN && (unsigned)d < (unsigned)NN) {
            int pos = atomicAdd(&g_cnt[d], 1);
            Edge ed; ed.s = s; ed.w = g_dinv[s] * g_dinv[d];
            g_edge[pos] = ed;
        }
    }
}

// ---------------- aggregation ------------------------------------------------
template <int CH, int GRP, int VEC, bool BIAS, bool RELU>
__global__ void k_agg(const float* __restrict__ hext, int hs,
                      float* __restrict__ oext, int ds,
                      const float* __restrict__ bias) {
    const float* __restrict__ h = sel_src(hext, hs);
    float* __restrict__ out = sel_dst(oext, ds);
    int node = (blockIdx.x * blockDim.x + threadIdx.x) / GRP;
    int sub  = threadIdx.x % GRP;
    if (node >= NN) return;
    constexpr int NV = CH / VEC;
    bool act = (NV == GRP) || (sub < NV);
    int c0 = sub * VEC;

    float acc[VEC];
#pragma unroll
    for (int v = 0; v < VEC; v++) acc[v] = 0.f;

    float sd = g_dinv[node];
    sd *= sd;
    if (act) {
        const float* hr = h + (size_t)node * CH + c0;
#pragma unroll
        for (int v = 0; v < VEC; v++) acc[v] = sd * hr[v];
    }

    int e = g_rowptr[node], end = g_rowptr[node + 1];
#pragma unroll 2
    for (; e < end; e++) {
        Edge ed = g_edge[e];
        const float* hr = h + (size_t)ed.s * CH + c0;
        if (act) {
            if (VEC == 4) {
                float4 v4 = *(const float4*)hr;
                acc[0] += ed.w * v4.x; acc[1] += ed.w * v4.y;
                acc[2] += ed.w * v4.z; acc[3] += ed.w * v4.w;
            } else if (VEC == 2) {
                float2 v2 = *(const float2*)hr;
                acc[0] += ed.w * v2.x; acc[1] += ed.w * v2.y;
            } else {
                acc[0] += ed.w * hr[0];
            }
        }
    }

    if (act) {
        float* orow = out + (size_t)node * CH + c0;
#pragma unroll
        for (int v = 0; v < VEC; v++) {
            float t = acc[v];
            if (BIAS) t += bias[c0 + v];
            if (RELU) t = fmaxf(t, 0.f);
            acc[v] = t;
        }
        if (VEC == 4)      *(float4*)orow = make_float4(acc[0], acc[1], acc[2], acc[3]);
        else if (VEC == 2) *(float2*)orow = make_float2(acc[0], acc[1]);
        else               orow[0] = acc[0];
    }
}

// ---------------- scalar GEMM (layer 1 only: 12->64) -------------------------
template <int IN, int OUT, int KC, bool BIAS, bool RELU>
__global__ void k_gemm(const float* __restrict__ hext, int hs,
                       const float* __restrict__ W,
                       const float* __restrict__ b,
                       float* __restrict__ oext, int ds) {
    const float* __restrict__ h = sel_src(hext, hs);
    float* __restrict__ out = sel_dst(oext, ds);
    constexpr int BN = 32;
    constexpr int HS = BN + 4;
    __shared__ float Wsm[KC * OUT];
    __shared__ float Hsm[KC * HS];

    int tid = threadIdx.y * blockDim.x + threadIdx.x;
    int nthreads = blockDim.x * blockDim.y;
    int n0blk = blockIdx.x * BN;

    int c0 = threadIdx.x * 4;
    int n0 = threadIdx.y * 4;
    float acc[4][4];
#pragma unroll
    for (int a = 0; a < 4; a++)
#pragma unroll
        for (int c = 0; c < 4; c++) acc[a][c] = 0.f;

    for (int kc0 = 0; kc0 < IN; kc0 += KC) {
        for (int i = tid; i < KC * OUT; i += nthreads) Wsm[i] = W[kc0 * OUT + i];
        for (int i = tid; i < BN * KC; i += nthreads) {
            int n = i / KC, k = i % KC;
            int node = n0blk + n;
            Hsm[k * HS + n] = (node < NN) ? h[(size_t)node * IN + kc0 + k] : 0.f;
        }
        __syncthreads();

#pragma unroll 4
        for (int k = 0; k < KC; k++) {
            float4 hv4 = *(const float4*)&Hsm[k * HS + n0];
            float4 wv4 = *(const float4*)&Wsm[k * OUT + c0];
            float hv[4] = {hv4.x, hv4.y, hv4.z, hv4.w};
            float wv[4] = {wv4.x, wv4.y, wv4.z, wv4.w};
#pragma unroll
            for (int a = 0; a < 4; a++)
#pragma unroll
                for (int c = 0; c < 4; c++) acc[a][c] += hv[a] * wv[c];
        }
        __syncthreads();
    }

    float bv[4] = {0.f, 0.f, 0.f, 0.f};
    if (BIAS) {
        float4 b4 = *(const float4*)&b[c0];
        bv[0] = b4.x; bv[1] = b4.y; bv[2] = b4.z; bv[3] = b4.w;
    }
#pragma unroll
    for (int a = 0; a < 4; a++) {
        int node = n0blk + n0 + a;
        if (node < NN) {
            float t0 = acc[a][0] + bv[0];
            float t1 = acc[a][1] + bv[1];
            float t2 = acc[a][2] + bv[2];
            float t3 = acc[a][3] + bv[3];
            if (RELU) {
                t0 = fmaxf(t0, 0.f); t1 = fmaxf(t1, 0.f);
                t2 = fmaxf(t2, 0.f); t3 = fmaxf(t3, 0.f);
            }
            float4 o; o.x = t0; o.y = t1; o.z = t2; o.w = t3;
            *(float4*)&out[(size_t)node * OUT + c0] = o;
        }
    }
}

// ---------------- tf32 mma.sync GEMM (layers 2 & 3) --------------------------
// out[128,OUT] per block = h[128,K] @ W[K,OUT] (+b, relu).
// 256 threads = 8 warps; warp w owns rows [16w, 16w+16). K chunked at KC=32.
// tf32 conversion done once at staging. Strides: A=40 (8g+t4 banks unique),
// B=OUT+8 (8t4+g unique) -> conflict-free fragment loads.
template <int K, int OUT, bool BIAS, bool RELU>
__global__ __launch_bounds__(256) void k_mmagemm(
        const float* __restrict__ hext, int hs,
        const float* __restrict__ W,
        const float* __restrict__ b,
        float* __restrict__ oext, int ds) {
    const float* __restrict__ h = sel_src(hext, hs);
    float* __restrict__ out = sel_dst(oext, ds);
    constexpr int KC = 32;
    constexpr int NCH = K / KC;
    constexpr int AS = 40;        // A row stride (uint32)
    constexpr int BS = OUT + 8;   // B row stride (uint32)
    constexpr int NT = OUT / 8;   // n-tiles per warp
    __shared__ uint32_t Asm[128 * AS];
    __shared__ uint32_t Bsm[KC * BS];

    int tid = threadIdx.x;
    int wid = tid >> 5, lane = tid & 31;
    int g = lane >> 2, t4 = lane & 3;
    int tile0 = blockIdx.x * 128;

    float acc[NT][4];
#pragma unroll
    for (int nt = 0; nt < NT; nt++)
#pragma unroll
        for (int j = 0; j < 4; j++) acc[nt][j] = 0.f;

    for (int c = 0; c < NCH; c++) {
        int kc = c * KC;
        // stage A: 128 rows x KC floats -> tf32 (coalesced float4 from h)
        for (int i = tid; i < 128 * (KC / 4); i += 256) {
            int row = i >> 3, j = i & 7;       // KC/4 == 8
            int node = tile0 + row;
            float4 v = make_float4(0.f, 0.f, 0.f, 0.f);
            if (node < NN) v = *(const float4*)&h[(size_t)node * K + kc + 4 * j];
            uint4 t;
            t.x = f2tf32(v.x); t.y = f2tf32(v.y);
            t.z = f2tf32(v.z); t.w = f2tf32(v.w);
            *(uint4*)&Asm[row * AS + 4 * j] = t;
        }
        // stage B: KC x OUT from W rows (coalesced float4)
        for (int i = tid; i < KC * (OUT / 4); i += 256) {
            int k = i / (OUT / 4), j = i % (OUT / 4);
            float4 v = *(const float4*)&W[(size_t)(kc + k) * OUT + 4 * j];
            uint4 t;
            t.x = f2tf32(v.x); t.y = f2tf32(v.y);
            t.z = f2tf32(v.z); t.w = f2tf32(v.w);
            *(uint4*)&Bsm[k * BS + 4 * j] = t;
        }
        __syncthreads();

#pragma unroll
        for (int ks = 0; ks < KC / 8; ks++) {
            int k0 = ks * 8;
            uint32_t a[4];
            const uint32_t* ar0 = &Asm[(wid * 16 + g) * AS + k0 + t4];
            const uint32_t* ar1 = &Asm[(wid * 16 + g + 8) * AS + k0 + t4];
            a[0] = ar0[0]; a[1] = ar1[0]; a[2] = ar0[4]; a[3] = ar1[4];
#pragma unroll
            for (int nt = 0; nt < NT; nt++) {
                uint32_t bb[2];
                bb[0] = Bsm[(k0 + t4) * BS + nt * 8 + g];
                bb[1] = Bsm[(k0 + t4 + 4) * BS + nt * 8 + g];
                mma_tf32_16n8k8(acc[nt], a, bb);
            }
        }
        __syncthreads();
    }

    // epilogue: c0,c1 -> (row g, cols nt*8+2t4, +1); c2,c3 -> row g+8
    int node0 = tile0 + wid * 16 + g;
    int node1 = node0 + 8;
#pragma unroll
    for (int nt = 0; nt < NT; nt++) {
        int col = nt * 8 + 2 * t4;
        float2 bv = make_float2(0.f, 0.f);
        if (BIAS) bv = *(const float2*)&b[col];
        float2 o0 = make_float2(acc[nt][0] + bv.x, acc[nt][1] + bv.y);
        float2 o1 = make_float2(acc[nt][2] + bv.x, acc[nt][3] + bv.y);
        if (RELU) {
            o0.x = fmaxf(o0.x, 0.f); o0.y = fmaxf(o0.y, 0.f);
            o1.x = fmaxf(o1.x, 0.f); o1.y = fmaxf(o1.y, 0.f);
        }
        if (node0 < NN) *(float2*)&out[(size_t)node0 * OUT + col] = o0;
        if (node1 < NN) *(float2*)&out[(size_t)node1 * OUT + col] = o1;
    }
}

// ---------------- launch ------------------------------------------------------
extern "C" void kernel_launch(void* const* d_in, const int* in_sizes, int n_in,
                              void* d_out, int out_size) {
    const float* x  = (const float*)d_in[0];
    const int* ei32 = (const int*)d_in[1];
    const float* W1 = (const float*)d_in[2];
    const float* b1 = (const float*)d_in[3];
    const float* W2 = (const float*)d_in[4];
    const float* b2 = (const float*)d_in[5];
    const float* W3 = (const float*)d_in[6];
    const float* b3 = (const float*)d_in[7];
    float* out      = (float*)d_out;
    int E = in_sizes[1] / 2;

    // CSR build
    k_init<<<(NN + 255) / 256, 256>>>(ei32);
    k_count<<<(E + 255) / 256, 256>>>(ei32, E);
    k_scan1<<<SCAN_NBLK, 256>>>();
    k_scan2<<<1, 128>>>();
    k_scan3<<<SCAN_NBLK, 256>>>();
    k_scatter<<<(E + 255) / 256, 256>>>(ei32, E);

    int aggW = (NN * 32 + 255) / 256;
    int aggH = (NN * 16 + 255) / 256;
    int gScalar = (NN + 31) / 32;
    int gMMA = (NN + 127) / 128;  // 782

    // layer 1: agg(x)[12] -> scalar GEMM 12->64 (+b1, relu)
    k_agg<12, 16, 1, false, false><<<aggH, 256>>>(x, 0, nullptr, 1, nullptr);
    k_gemm<12, 64, 12, true, true><<<gScalar, dim3(16, 8)>>>(nullptr, 1, W1, b1, nullptr, 2);

    // layer 2: agg[64] -> tf32 MMA GEMM 64->128 (+b2, relu)
    k_agg<64, 32, 2, false, false><<<aggW, 256>>>(nullptr, 2, nullptr, 1, nullptr);
    k_mmagemm<64, 128, true, true><<<gMMA, 256>>>(nullptr, 1, W2, b2, nullptr, 2);

    // layer 3: tf32 MMA GEMM 128->96 -> agg[96] (+b3) -> out
    k_mmagemm<128, 96, false, false><<<gMMA, 256>>>(nullptr, 2, W3, nullptr, nullptr, 1);
    k_agg<96, 32, 4, true, false><<<aggW, 256>>>(nullptr, 1, out, 0, b3);
}

// round 8
// speedup vs baseline: 1.4465x; 1.1066x over previous
#include <cuda_runtime.h>
#include <cstdint>

typedef unsigned long long ull;

constexpr int NN = 100000;   // nodes
constexpr int EE = 1600000;  // edges (no self loops)
constexpr int SCAN_NBLK = (NN + 1023) / 1024;  // 98

struct __align__(8) Edge { int s; float w; };

// ---------------- static device scratch --------------------------------------
__device__ int   g_is64;
__device__ int   g_cnt[NN];
__device__ int   g_rowptr[NN + 1];
__device__ int   g_bsum[128];
__device__ float g_dinv[NN];
__device__ Edge  g_edge[EE];
__device__ float g_buf1[(size_t)NN * 128];
__device__ float g_buf2[(size_t)NN * 128];

__device__ __forceinline__ const float* sel_src(const float* ext, int s) {
    return s == 0 ? ext : (s == 1 ? (const float*)g_buf1 : (const float*)g_buf2);
}
__device__ __forceinline__ float* sel_dst(float* ext, int s) {
    return s == 0 ? ext : (s == 1 ? (float*)g_buf1 : (float*)g_buf2);
}

// tf32 helpers (arch-agnostic PTX, sm_80+)
__device__ __forceinline__ uint32_t f2tf32(float f) {
    uint32_t r;
    asm("cvt.rna.tf32.f32 %0, %1;" : "=r"(r) : "f"(f));
    return r;
}
__device__ __forceinline__ void mma_tf32_16n8k8(float* c, const uint32_t* a,
                                                const uint32_t* b) {
    asm volatile(
        "mma.sync.aligned.m16n8k8.row.col.f32.tf32.tf32.f32 "
        "{%0,%1,%2,%3}, {%4,%5,%6,%7}, {%8,%9}, {%0,%1,%2,%3};"
        : "+f"(c[0]), "+f"(c[1]), "+f"(c[2]), "+f"(c[3])
        : "r"(a[0]), "r"(a[1]), "r"(a[2]), "r"(a[3]), "r"(b[0]), "r"(b[1]));
}

// ---------------- init + dtype detect ----------------------------------------
__global__ void k_init(const int* __restrict__ w) {
    int i = blockIdx.x * blockDim.x + threadIdx.x;
    if (i < NN) g_cnt[i] = 0;
    if (blockIdx.x == 0 && threadIdx.x < 32) {
        int lane = threadIdx.x;
        int acc = 0;
        for (int j = lane; j < 1024; j += 32) acc |= w[2 * j + 1];
#pragma unroll
        for (int off = 16; off > 0; off >>= 1)
            acc |= __shfl_xor_sync(0xffffffffu, acc, off);
        if (lane == 0) g_is64 = (acc == 0) ? 1 : 0;
    }
}

__device__ __forceinline__ int load_idx(const int* __restrict__ w, int pos, int is64) {
    if (is64) return ((const int2*)w)[pos].x;
    return w[pos];
}

// 4 edges per thread, vectorized dst reads
__global__ void k_count(const int* __restrict__ w, int E) {
    int e0 = (blockIdx.x * blockDim.x + threadIdx.x) * 4;
    if (e0 >= E) return;
    int is64 = g_is64;
    int d[4];
    int nv = min(4, E - e0);
    if (is64) {
        if (nv == 4 && ((E + e0) & 1) == 0) {
            int4 a = *(const int4*)&w[2 * (E + e0)];
            int4 b = *(const int4*)&w[2 * (E + e0) + 4];
            d[0] = a.x; d[1] = a.z; d[2] = b.x; d[3] = b.z;
        } else {
            for (int j = 0; j < nv; j++) d[j] = ((const int2*)w)[E + e0 + j].x;
        }
    } else {
        if (nv == 4 && ((E + e0) & 3) == 0) {
            int4 a = *(const int4*)&w[E + e0];
            d[0] = a.x; d[1] = a.y; d[2] = a.z; d[3] = a.w;
        } else {
            for (int j = 0; j < nv; j++) d[j] = w[E + e0 + j];
        }
    }
    for (int j = 0; j < nv; j++)
        if ((unsigned)d[j] < (unsigned)NN) atomicAdd(&g_cnt[d[j]], 1);
}

__global__ void k_scan1() {
    __shared__ int s[256];
    int b = blockIdx.x, tid = threadIdx.x;
    int base = b * 1024 + tid * 4;
    int local = 0;
#pragma unroll
    for (int j = 0; j < 4; j++) {
        int i = base + j;
        if (i < NN) {
            int c = g_cnt[i];
            local += c;
            g_dinv[i] = rsqrtf((float)(c + 1));
        }
    }
    s[tid] = local;
    __syncthreads();
    for (int off = 128; off > 0; off >>= 1) {
        if (tid < off) s[tid] += s[tid + off];
        __syncthreads();
    }
    if (tid == 0) g_bsum[b] = s[0];
}

__global__ void k_scan2() {
    __shared__ int s[128];
    int tid = threadIdx.x;
    int v = (tid < SCAN_NBLK) ? g_bsum[tid] : 0;
    s[tid] = v;
    __syncthreads();
    for (int off = 1; off < 128; off <<= 1) {
        int t = (tid >= off) ? s[tid - off] : 0;
        __syncthreads();
        s[tid] += t;
        __syncthreads();
    }
    if (tid < SCAN_NBLK) g_bsum[tid] = s[tid] - v;
    if (tid == 127) g_rowptr[NN] = s[127];
}

__global__ void k_scan3() {
    __shared__ int s[256];
    int b = blockIdx.x, tid = threadIdx.x;
    int base = b * 1024 + tid * 4;
    int v[4];
#pragma unroll
    for (int j = 0; j < 4; j++) {
        int i = base + j;
        v[j] = (i < NN) ? g_cnt[i] : 0;
    }
    int local = v[0] + v[1] + v[2] + v[3];
    s[tid] = local;
    __syncthreads();
    for (int off = 1; off < 256; off <<= 1) {
        int t = (tid >= off) ? s[tid - off] : 0;
        __syncthreads();
        s[tid] += t;
        __syncthreads();
    }
    int excl = s[tid] - local + g_bsum[b];
#pragma unroll
    for (int j = 0; j < 4; j++) {
        int i = base + j;
        if (i < NN) { g_rowptr[i] = excl; g_cnt[i] = excl; }
        excl += v[j];
    }
}

__global__ void k_scatter(const int* __restrict__ w, int E) {
    int e = blockIdx.x * blockDim.x + threadIdx.x;
    if (e < E) {
        int is64 = g_is64;
        int s = load_idx(w, e, is64);
        int d = load_idx(w, E + e, is64);
        if ((unsigned)s < (unsigned)NN && (unsigned)d < (unsigned)NN) {
            int pos = atomicAdd(&g_cnt[d], 1);
            Edge ed; ed.s = s; ed.w = g_dinv[s] * g_dinv[d];
            g_edge[pos] = ed;
        }
    }
}

// ---------------- aggregation: GRP lanes/node, VEC floats/lane ---------------
// out[i] = dinv[i]^2 * h[i] + sum_e w_e * h[src_e]   (+bias, relu optional)
// 2-edge unrolled mainloop: both edge descriptors + both rows in flight.
template <int CH, int GRP, int VEC, bool BIAS, bool RELU>
__global__ void k_agg(const float* __restrict__ hext, int hs,
                      float* __restrict__ oext, int ds,
                      const float* __restrict__ bias) {
    const float* __restrict__ h = sel_src(hext, hs);
    float* __restrict__ out = sel_dst(oext, ds);
    int node = (blockIdx.x * blockDim.x + threadIdx.x) / GRP;
    int sub  = threadIdx.x % GRP;
    if (node >= NN) return;
    constexpr int NV = CH / VEC;
    bool act = (NV == GRP) || (sub < NV);
    int c0 = sub * VEC;

    float acc[VEC];
#pragma unroll
    for (int v = 0; v < VEC; v++) acc[v] = 0.f;

    float sd = g_dinv[node];
    sd *= sd;
    if (act) {
        const float* hr = h + (size_t)node * CH + c0;
#pragma unroll
        for (int v = 0; v < VEC; v++) acc[v] = sd * hr[v];
    }

    int e = g_rowptr[node];
    const int end = g_rowptr[node + 1];

    // 2-edge unrolled body (loads for both edges issued before FMAs)
    for (; e + 2 <= end; e += 2) {
        Edge e0 = g_edge[e];
        Edge e1 = g_edge[e + 1];
        const float* r0 = h + (size_t)e0.s * CH + c0;
        const float* r1 = h + (size_t)e1.s * CH + c0;
        if (act) {
            if (VEC == 4) {
                float4 a = *(const float4*)r0;
                float4 b4 = *(const float4*)r1;
                acc[0] += e0.w * a.x + e1.w * b4.x;
                acc[1] += e0.w * a.y + e1.w * b4.y;
                acc[2] += e0.w * a.z + e1.w * b4.z;
                acc[3] += e0.w * a.w + e1.w * b4.w;
            } else if (VEC == 2) {
                float2 a = *(const float2*)r0;
                float2 b2 = *(const float2*)r1;
                acc[0] += e0.w * a.x + e1.w * b2.x;
                acc[1] += e0.w * a.y + e1.w * b2.y;
            } else {
                float a = r0[0], b1 = r1[0];
                acc[0] += e0.w * a + e1.w * b1;
            }
        }
    }
    if (e < end) {
        Edge e0 = g_edge[e];
        const float* r0 = h + (size_t)e0.s * CH + c0;
        if (act) {
            if (VEC == 4) {
                float4 a = *(const float4*)r0;
                acc[0] += e0.w * a.x; acc[1] += e0.w * a.y;
                acc[2] += e0.w * a.z; acc[3] += e0.w * a.w;
            } else if (VEC == 2) {
                float2 a = *(const float2*)r0;
                acc[0] += e0.w * a.x; acc[1] += e0.w * a.y;
            } else {
                acc[0] += e0.w * r0[0];
            }
        }
    }

    if (act) {
        float* orow = out + (size_t)node * CH + c0;
#pragma unroll
        for (int v = 0; v < VEC; v++) {
            float t = acc[v];
            if (BIAS) t += bias[c0 + v];
            if (RELU) t = fmaxf(t, 0.f);
            acc[v] = t;
        }
        if (VEC == 4)      *(float4*)orow = make_float4(acc[0], acc[1], acc[2], acc[3]);
        else if (VEC == 2) *(float2*)orow = make_float2(acc[0], acc[1]);
        else               orow[0] = acc[0];
    }
}

// ---------------- scalar GEMM (layer 1 only: 12->64) -------------------------
template <int IN, int OUT, int KC, bool BIAS, bool RELU>
__global__ void k_gemm(const float* __restrict__ hext, int hs,
                       const float* __restrict__ W,
                       const float* __restrict__ b,
                       float* __restrict__ oext, int ds) {
    const float* __restrict__ h = sel_src(hext, hs);
    float* __restrict__ out = sel_dst(oext, ds);
    constexpr int BN = 32;
    constexpr int HS = BN + 4;
    __shared__ float Wsm[KC * OUT];
    __shared__ float Hsm[KC * HS];

    int tid = threadIdx.y * blockDim.x + threadIdx.x;
    int nthreads = blockDim.x * blockDim.y;
    int n0blk = blockIdx.x * BN;

    int c0 = threadIdx.x * 4;
    int n0 = threadIdx.y * 4;
    float acc[4][4];
#pragma unroll
    for (int a = 0; a < 4; a++)
#pragma unroll
        for (int c = 0; c < 4; c++) acc[a][c] = 0.f;

    for (int kc0 = 0; kc0 < IN; kc0 += KC) {
        for (int i = tid; i < KC * OUT; i += nthreads) Wsm[i] = W[kc0 * OUT + i];
        for (int i = tid; i < BN * KC; i += nthreads) {
            int n = i / KC, k = i % KC;
            int node = n0blk + n;
            Hsm[k * HS + n] = (node < NN) ? h[(size_t)node * IN + kc0 + k] : 0.f;
        }
        __syncthreads();

#pragma unroll 4
        for (int k = 0; k < KC; k++) {
            float4 hv4 = *(const float4*)&Hsm[k * HS + n0];
            float4 wv4 = *(const float4*)&Wsm[k * OUT + c0];
            float hv[4] = {hv4.x, hv4.y, hv4.z, hv4.w};
            float wv[4] = {wv4.x, wv4.y, wv4.z, wv4.w};
#pragma unroll
            for (int a = 0; a < 4; a++)
#pragma unroll
                for (int c = 0; c < 4; c++) acc[a][c] += hv[a] * wv[c];
        }
        __syncthreads();
    }

    float bv[4] = {0.f, 0.f, 0.f, 0.f};
    if (BIAS) {
        float4 b4 = *(const float4*)&b[c0];
        bv[0] = b4.x; bv[1] = b4.y; bv[2] = b4.z; bv[3] = b4.w;
    }
#pragma unroll
    for (int a = 0; a < 4; a++) {
        int node = n0blk + n0 + a;
        if (node < NN) {
            float t0 = acc[a][0] + bv[0];
            float t1 = acc[a][1] + bv[1];
            float t2 = acc[a][2] + bv[2];
            float t3 = acc[a][3] + bv[3];
            if (RELU) {
                t0 = fmaxf(t0, 0.f); t1 = fmaxf(t1, 0.f);
                t2 = fmaxf(t2, 0.f); t3 = fmaxf(t3, 0.f);
            }
            float4 o; o.x = t0; o.y = t1; o.z = t2; o.w = t3;
            *(float4*)&out[(size_t)node * OUT + c0] = o;
        }
    }
}

// ---------------- tf32 mma.sync GEMM (layers 2 & 3) --------------------------
template <int K, int OUT, bool BIAS, bool RELU>
__global__ __launch_bounds__(256) void k_mmagemm(
        const float* __restrict__ hext, int hs,
        const float* __restrict__ W,
        const float* __restrict__ b,
        float* __restrict__ oext, int ds) {
    const float* __restrict__ h = sel_src(hext, hs);
    float* __restrict__ out = sel_dst(oext, ds);
    constexpr int KC = 32;
    constexpr int NCH = K / KC;
    constexpr int AS = 40;        // A row stride (uint32)
    constexpr int BS = OUT + 8;   // B row stride (uint32)
    constexpr int NT = OUT / 8;   // n-tiles per warp
    __shared__ uint32_t Asm[128 * AS];
    __shared__ uint32_t Bsm[KC * BS];

    int tid = threadIdx.x;
    int wid = tid >> 5, lane = tid & 31;
    int g = lane >> 2, t4 = lane & 3;
    int tile0 = blockIdx.x * 128;

    float acc[NT][4];
#pragma unroll
    for (int nt = 0; nt < NT; nt++)
#pragma unroll
        for (int j = 0; j < 4; j++) acc[nt][j] = 0.f;

    for (int c = 0; c < NCH; c++) {
        int kc = c * KC;
        for (int i = tid; i < 128 * (KC / 4); i += 256) {
            int row = i >> 3, j = i & 7;
            int node = tile0 + row;
            float4 v = make_float4(0.f, 0.f, 0.f, 0.f);
            if (node < NN) v = *(const float4*)&h[(size_t)node * K + kc + 4 * j];
            uint4 t;
            t.x = f2tf32(v.x); t.y = f2tf32(v.y);
            t.z = f2tf32(v.z); t.w = f2tf32(v.w);
            *(uint4*)&Asm[row * AS + 4 * j] = t;
        }
        for (int i = tid; i < KC * (OUT / 4); i += 256) {
            int k = i / (OUT / 4), j = i % (OUT / 4);
            float4 v = *(const float4*)&W[(size_t)(kc + k) * OUT + 4 * j];
            uint4 t;
            t.x = f2tf32(v.x); t.y = f2tf32(v.y);
            t.z = f2tf32(v.z); t.w = f2tf32(v.w);
            *(uint4*)&Bsm[k * BS + 4 * j] = t;
        }
        __syncthreads();

#pragma unroll
        for (int ks = 0; ks < KC / 8; ks++) {
            int k0 = ks * 8;
            uint32_t a[4];
            const uint32_t* ar0 = &Asm[(wid * 16 + g) * AS + k0 + t4];
            const uint32_t* ar1 = &Asm[(wid * 16 + g + 8) * AS + k0 + t4];
            a[0] = ar0[0]; a[1] = ar1[0]; a[2] = ar0[4]; a[3] = ar1[4];
#pragma unroll
            for (int nt = 0; nt < NT; nt++) {
                uint32_t bb[2];
                bb[0] = Bsm[(k0 + t4) * BS + nt * 8 + g];
                bb[1] = Bsm[(k0 + t4 + 4) * BS + nt * 8 + g];
                mma_tf32_16n8k8(acc[nt], a, bb);
            }
        }
        __syncthreads();
    }

    int node0 = tile0 + wid * 16 + g;
    int node1 = node0 + 8;
#pragma unroll
    for (int nt = 0; nt < NT; nt++) {
        int col = nt * 8 + 2 * t4;
        float2 bv = make_float2(0.f, 0.f);
        if (BIAS) bv = *(const float2*)&b[col];
        float2 o0 = make_float2(acc[nt][0] + bv.x, acc[nt][1] + bv.y);
        float2 o1 = make_float2(acc[nt][2] + bv.x, acc[nt][3] + bv.y);
        if (RELU) {
            o0.x = fmaxf(o0.x, 0.f); o0.y = fmaxf(o0.y, 0.f);
            o1.x = fmaxf(o1.x, 0.f); o1.y = fmaxf(o1.y, 0.f);
        }
        if (node0 < NN) *(float2*)&out[(size_t)node0 * OUT + col] = o0;
        if (node1 < NN) *(float2*)&out[(size_t)node1 * OUT + col] = o1;
    }
}

// ---------------- launch ------------------------------------------------------
extern "C" void kernel_launch(void* const* d_in, const int* in_sizes, int n_in,
                              void* d_out, int out_size) {
    const float* x  = (const float*)d_in[0];
    const int* ei32 = (const int*)d_in[1];
    const float* W1 = (const float*)d_in[2];
    const float* b1 = (const float*)d_in[3];
    const float* W2 = (const float*)d_in[4];
    const float* b2 = (const float*)d_in[5];
    const float* W3 = (const float*)d_in[6];
    const float* b3 = (const float*)d_in[7];
    float* out      = (float*)d_out;
    int E = in_sizes[1] / 2;

    // CSR build
    k_init<<<(NN + 255) / 256, 256>>>(ei32);
    k_count<<<(E / 4 + 255) / 256, 256>>>(ei32, E);
    k_scan1<<<SCAN_NBLK, 256>>>();
    k_scan2<<<1, 128>>>();
    k_scan3<<<SCAN_NBLK, 256>>>();
    k_scatter<<<(E + 255) / 256, 256>>>(ei32, E);

    int aggW = (NN * 32 + 255) / 256;   // GRP=32
    int aggH = (NN * 16 + 255) / 256;   // GRP=16
    int gScalar = (NN + 31) / 32;
    int gMMA = (NN + 127) / 128;  // 782

    // layer 1: agg(x)[12] -> scalar GEMM 12->64 (+b1, relu)
    k_agg<12, 16, 1, false, false><<<aggH, 256>>>(x, 0, nullptr, 1, nullptr);
    k_gemm<12, 64, 12, true, true><<<gScalar, dim3(16, 8)>>>(nullptr, 1, W1, b1, nullptr, 2);

    // layer 2: agg[64] (GRP16/VEC4) -> tf32 MMA GEMM 64->128 (+b2, relu)
    k_agg<64, 16, 4, false, false><<<aggH, 256>>>(nullptr, 2, nullptr, 1, nullptr);
    k_mmagemm<64, 128, true, true><<<gMMA, 256>>>(nullptr, 1, W2, b2, nullptr, 2);

    // layer 3: tf32 MMA GEMM 128->96 -> agg[96] (+b3) -> out
    k_mmagemm<128, 96, false, false><<<gMMA, 256>>>(nullptr, 2, W3, nullptr, nullptr, 1);
    k_agg<96, 32, 4, true, false><<<aggW, 256>>>(nullptr, 1, out, 0, b3);
}

// round 9
// speedup vs baseline: 1.5324x; 1.0594x over previous
#include <cuda_runtime.h>
#include <cuda_fp16.h>
#include <cstdint>

typedef unsigned long long ull;

constexpr int NN = 100000;   // nodes
constexpr int EE = 1600000;  // edges (no self loops)
constexpr int SCAN_NBLK = (NN + 1023) / 1024;  // 98

struct __align__(8) Edge { int s; float w; };

// ---------------- static device scratch --------------------------------------
__device__ int    g_is64;
__device__ int    g_cnt[NN];
__device__ int    g_rowptr[NN + 1];
__device__ int    g_bsum[128];
__device__ float  g_dinv[NN];
__device__ Edge   g_edge[EE];
__device__ float  g_buf1[(size_t)NN * 128];
__device__ float  g_buf2[(size_t)NN * 128];
__device__ __half g_hbuf[(size_t)NN * 96];   // fp16 feature buffer (64 or 96 ch)

__device__ __forceinline__ const float* sel_src(const float* ext, int s) {
    return s == 0 ? ext : (s == 1 ? (const float*)g_buf1 : (const float*)g_buf2);
}
__device__ __forceinline__ float* sel_dst(float* ext, int s) {
    return s == 0 ? ext : (s == 1 ? (float*)g_buf1 : (float*)g_buf2);
}

// tf32 helpers (arch-agnostic PTX, sm_80+)
__device__ __forceinline__ uint32_t f2tf32(float f) {
    uint32_t r;
    asm("cvt.rna.tf32.f32 %0, %1;" : "=r"(r) : "f"(f));
    return r;
}
__device__ __forceinline__ void mma_tf32_16n8k8(float* c, const uint32_t* a,
                                                const uint32_t* b) {
    asm volatile(
        "mma.sync.aligned.m16n8k8.row.col.f32.tf32.tf32.f32 "
        "{%0,%1,%2,%3}, {%4,%5,%6,%7}, {%8,%9}, {%0,%1,%2,%3};"
        : "+f"(c[0]), "+f"(c[1]), "+f"(c[2]), "+f"(c[3])
        : "r"(a[0]), "r"(a[1]), "r"(a[2]), "r"(a[3]), "r"(b[0]), "r"(b[1]));
}

// load 8 halfs (16B) -> 8 floats
__device__ __forceinline__ void ld_half8(const __half* p, float* f) {
    uint4 r = *(const uint4*)p;
    const __half2* h2 = (const __half2*)&r;
#pragma unroll
    for (int j = 0; j < 4; j++) {
        float2 t = __half22float2(h2[j]);
        f[2 * j] = t.x; f[2 * j + 1] = t.y;
    }
}

// ---------------- init + dtype detect ----------------------------------------
__global__ void k_init(const int* __restrict__ w) {
    int i = blockIdx.x * blockDim.x + threadIdx.x;
    if (i < NN) g_cnt[i] = 0;
    if (blockIdx.x == 0 && threadIdx.x < 32) {
        int lane = threadIdx.x;
        int acc = 0;
        for (int j = lane; j < 1024; j += 32) acc |= w[2 * j + 1];
#pragma unroll
        for (int off = 16; off > 0; off >>= 1)
            acc |= __shfl_xor_sync(0xffffffffu, acc, off);
        if (lane == 0) g_is64 = (acc == 0) ? 1 : 0;
    }
}

__device__ __forceinline__ int load_idx(const int* __restrict__ w, int pos, int is64) {
    if (is64) return ((const int2*)w)[pos].x;
    return w[pos];
}

// 4 edges per thread, vectorized dst reads
__global__ void k_count(const int* __restrict__ w, int E) {
    int e0 = (blockIdx.x * blockDim.x + threadIdx.x) * 4;
    if (e0 >= E) return;
    int is64 = g_is64;
    int d[4];
    int nv = min(4, E - e0);
    if (is64) {
        if (nv == 4 && ((E + e0) & 1) == 0) {
            int4 a = *(const int4*)&w[2 * (E + e0)];
            int4 b = *(const int4*)&w[2 * (E + e0) + 4];
            d[0] = a.x; d[1] = a.z; d[2] = b.x; d[3] = b.z;
        } else {
            for (int j = 0; j < nv; j++) d[j] = ((const int2*)w)[E + e0 + j].x;
        }
    } else {
        if (nv == 4 && ((E + e0) & 3) == 0) {
            int4 a = *(const int4*)&w[E + e0];
            d[0] = a.x; d[1] = a.y; d[2] = a.z; d[3] = a.w;
        } else {
            for (int j = 0; j < nv; j++) d[j] = w[E + e0 + j];
        }
    }
    for (int j = 0; j < nv; j++)
        if ((unsigned)d[j] < (unsigned)NN) atomicAdd(&g_cnt[d[j]], 1);
}

__global__ void k_scan1() {
    __shared__ int s[256];
    int b = blockIdx.x, tid = threadIdx.x;
    int base = b * 1024 + tid * 4;
    int local = 0;
#pragma unroll
    for (int j = 0; j < 4; j++) {
        int i = base + j;
        if (i < NN) {
            int c = g_cnt[i];
            local += c;
            g_dinv[i] = rsqrtf((float)(c + 1));
        }
    }
    s[tid] = local;
    __syncthreads();
    for (int off = 128; off > 0; off >>= 1) {
        if (tid < off) s[tid] += s[tid + off];
        __syncthreads();
    }
    if (tid == 0) g_bsum[b] = s[0];
}

__global__ void k_scan2() {
    __shared__ int s[128];
    int tid = threadIdx.x;
    int v = (tid < SCAN_NBLK) ? g_bsum[tid] : 0;
    s[tid] = v;
    __syncthreads();
    for (int off = 1; off < 128; off <<= 1) {
        int t = (tid >= off) ? s[tid - off] : 0;
        __syncthreads();
        s[tid] += t;
        __syncthreads();
    }
    if (tid < SCAN_NBLK) g_bsum[tid] = s[tid] - v;
    if (tid == 127) g_rowptr[NN] = s[127];
}

__global__ void k_scan3() {
    __shared__ int s[256];
    int b = blockIdx.x, tid = threadIdx.x;
    int base = b * 1024 + tid * 4;
    int v[4];
#pragma unroll
    for (int j = 0; j < 4; j++) {
        int i = base + j;
        v[j] = (i < NN) ? g_cnt[i] : 0;
    }
    int local = v[0] + v[1] + v[2] + v[3];
    s[tid] = local;
    __syncthreads();
    for (int off = 1; off < 256; off <<= 1) {
        int t = (tid >= off) ? s[tid - off] : 0;
        __syncthreads();
        s[tid] += t;
        __syncthreads();
    }
    int excl = s[tid] - local + g_bsum[b];
#pragma unroll
    for (int j = 0; j < 4; j++) {
        int i = base + j;
        if (i < NN) { g_rowptr[i] = excl; g_cnt[i] = excl; }
        excl += v[j];
    }
}

// 2 edges per thread, vectorized index loads
__global__ void k_scatter(const int* __restrict__ w, int E) {
    int e0 = (blockIdx.x * blockDim.x + threadIdx.x) * 2;
    if (e0 >= E) return;
    int is64 = g_is64;
    int nv = min(2, E - e0);
    int s[2], d[2];
    if (is64) {
        if (nv == 2 && ((E + e0) & 1) == 0) {
            int4 a = *(const int4*)&w[2 * e0];
            int4 b = *(const int4*)&w[2 * (E + e0)];
            s[0] = a.x; s[1] = a.z; d[0] = b.x; d[1] = b.z;
        } else {
            for (int j = 0; j < nv; j++) {
                s[j] = ((const int2*)w)[e0 + j].x;
                d[j] = ((const int2*)w)[E + e0 + j].x;
            }
        }
    } else {
        if (nv == 2 && ((E + e0) & 1) == 0) {
            int2 a = *(const int2*)&w[e0];
            int2 b = *(const int2*)&w[E + e0];
            s[0] = a.x; s[1] = a.y; d[0] = b.x; d[1] = b.y;
        } else {
            for (int j = 0; j < nv; j++) { s[j] = w[e0 + j]; d[j] = w[E + e0 + j]; }
        }
    }
    for (int j = 0; j < nv; j++) {
        if ((unsigned)s[j] < (unsigned)NN && (unsigned)d[j] < (unsigned)NN) {
            int pos = atomicAdd(&g_cnt[d[j]], 1);
            Edge ed; ed.s = s[j]; ed.w = g_dinv[s[j]] * g_dinv[d[j]];
            g_edge[pos] = ed;
        }
    }
}

// ---------------- aggregation: GRP lanes/node, VEC floats/lane ---------------
// INH: gather features from g_hbuf (fp16), accumulate fp32. Else fp32 via sel.
template <int CH, int GRP, int VEC, bool INH, bool BIAS, bool RELU>
__global__ void k_agg(const float* __restrict__ hext, int hs,
                      float* __restrict__ oext, int ds,
                      const float* __restrict__ bias) {
    const float* __restrict__ h = INH ? nullptr : sel_src(hext, hs);
    const __half* __restrict__ hh = INH ? (const __half*)g_hbuf : nullptr;
    float* __restrict__ out = sel_dst(oext, ds);
    int node = (blockIdx.x * blockDim.x + threadIdx.x) / GRP;
    int sub  = threadIdx.x % GRP;
    if (node >= NN) return;
    constexpr int NV = CH / VEC;
    bool act = (NV == GRP) || (sub < NV);
    int c0 = sub * VEC;

    float acc[VEC];
#pragma unroll
    for (int v = 0; v < VEC; v++) acc[v] = 0.f;

    float sd = g_dinv[node];
    sd *= sd;
    if (act) {
        if (INH) {
            float f[VEC];
            ld_half8(hh + (size_t)node * CH + c0, f);
#pragma unroll
            for (int v = 0; v < VEC; v++) acc[v] = sd * f[v];
        } else {
            const float* hr = h + (size_t)node * CH + c0;
#pragma unroll
            for (int v = 0; v < VEC; v++) acc[v] = sd * hr[v];
        }
    }

    int e = g_rowptr[node];
    const int end = g_rowptr[node + 1];

    for (; e + 2 <= end; e += 2) {
        Edge e0 = g_edge[e];
        Edge e1 = g_edge[e + 1];
        if (act) {
            if (INH) {
                float f0[VEC], f1[VEC];
                ld_half8(hh + (size_t)e0.s * CH + c0, f0);
                ld_half8(hh + (size_t)e1.s * CH + c0, f1);
#pragma unroll
                for (int v = 0; v < VEC; v++)
                    acc[v] += e0.w * f0[v] + e1.w * f1[v];
            } else {
                const float* r0 = h + (size_t)e0.s * CH + c0;
                const float* r1 = h + (size_t)e1.s * CH + c0;
                if (VEC == 4) {
                    float4 a = *(const float4*)r0;
                    float4 b4 = *(const float4*)r1;
                    acc[0] += e0.w * a.x + e1.w * b4.x;
                    acc[1] += e0.w * a.y + e1.w * b4.y;
                    acc[2] += e0.w * a.z + e1.w * b4.z;
                    acc[3] += e0.w * a.w + e1.w * b4.w;
                } else {
                    acc[0] += e0.w * r0[0] + e1.w * r1[0];
                }
            }
        }
    }
    if (e < end) {
        Edge e0 = g_edge[e];
        if (act) {
            if (INH) {
                float f0[VEC];
                ld_half8(hh + (size_t)e0.s * CH + c0, f0);
#pragma unroll
                for (int v = 0; v < VEC; v++) acc[v] += e0.w * f0[v];
            } else {
                const float* r0 = h + (size_t)e0.s * CH + c0;
                if (VEC == 4) {
                    float4 a = *(const float4*)r0;
                    acc[0] += e0.w * a.x; acc[1] += e0.w * a.y;
                    acc[2] += e0.w * a.z; acc[3] += e0.w * a.w;
                } else {
                    acc[0] += e0.w * r0[0];
                }
            }
        }
    }

    if (act) {
        float* orow = out + (size_t)node * CH + c0;
#pragma unroll
        for (int v = 0; v < VEC; v++) {
            float t = acc[v];
            if (BIAS) t += bias[c0 + v];
            if (RELU) t = fmaxf(t, 0.f);
            acc[v] = t;
        }
        if (VEC == 8) {
            *(float4*)&orow[0] = make_float4(acc[0], acc[1], acc[2], acc[3]);
            *(float4*)&orow[4] = make_float4(acc[4], acc[5], acc[6], acc[7]);
        } else if (VEC == 4) {
            *(float4*)orow = make_float4(acc[0], acc[1], acc[2], acc[3]);
        } else {
            orow[0] = acc[0];
        }
    }
}

// ---------------- scalar GEMM (layer 1: 12->64), optional half output --------
template <int IN, int OUT, int KC, bool BIAS, bool RELU, bool HOUT>
__global__ void k_gemm(const float* __restrict__ hext, int hs,
                       const float* __restrict__ W,
                       const float* __restrict__ b,
                       float* __restrict__ oext, int ds) {
    const float* __restrict__ h = sel_src(hext, hs);
    float* __restrict__ out = HOUT ? nullptr : sel_dst(oext, ds);
    __half* __restrict__ hout = HOUT ? (__half*)g_hbuf : nullptr;
    constexpr int BN = 32;
    constexpr int HS = BN + 4;
    __shared__ float Wsm[KC * OUT];
    __shared__ float Hsm[KC * HS];

    int tid = threadIdx.y * blockDim.x + threadIdx.x;
    int nthreads = blockDim.x * blockDim.y;
    int n0blk = blockIdx.x * BN;

    int c0 = threadIdx.x * 4;
    int n0 = threadIdx.y * 4;
    float acc[4][4];
#pragma unroll
    for (int a = 0; a < 4; a++)
#pragma unroll
        for (int c = 0; c < 4; c++) acc[a][c] = 0.f;

    for (int kc0 = 0; kc0 < IN; kc0 += KC) {
        for (int i = tid; i < KC * OUT; i += nthreads) Wsm[i] = W[kc0 * OUT + i];
        for (int i = tid; i < BN * KC; i += nthreads) {
            int n = i / KC, k = i % KC;
            int node = n0blk + n;
            Hsm[k * HS + n] = (node < NN) ? h[(size_t)node * IN + kc0 + k] : 0.f;
        }
        __syncthreads();

#pragma unroll 4
        for (int k = 0; k < KC; k++) {
            float4 hv4 = *(const float4*)&Hsm[k * HS + n0];
            float4 wv4 = *(const float4*)&Wsm[k * OUT + c0];
            float hv[4] = {hv4.x, hv4.y, hv4.z, hv4.w};
            float wv[4] = {wv4.x, wv4.y, wv4.z, wv4.w};
#pragma unroll
            for (int a = 0; a < 4; a++)
#pragma unroll
                for (int c = 0; c < 4; c++) acc[a][c] += hv[a] * wv[c];
        }
        __syncthreads();
    }

    float bv[4] = {0.f, 0.f, 0.f, 0.f};
    if (BIAS) {
        float4 b4 = *(const float4*)&b[c0];
        bv[0] = b4.x; bv[1] = b4.y; bv[2] = b4.z; bv[3] = b4.w;
    }
#pragma unroll
    for (int a = 0; a < 4; a++) {
        int node = n0blk + n0 + a;
        if (node < NN) {
            float t0 = acc[a][0] + bv[0];
            float t1 = acc[a][1] + bv[1];
            float t2 = acc[a][2] + bv[2];
            float t3 = acc[a][3] + bv[3];
            if (RELU) {
                t0 = fmaxf(t0, 0.f); t1 = fmaxf(t1, 0.f);
                t2 = fmaxf(t2, 0.f); t3 = fmaxf(t3, 0.f);
            }
            if (HOUT) {
                __half2 p0 = __floats2half2_rn(t0, t1);
                __half2 p1 = __floats2half2_rn(t2, t3);
                *(__half2*)&hout[(size_t)node * OUT + c0] = p0;
                *(__half2*)&hout[(size_t)node * OUT + c0 + 2] = p1;
            } else {
                float4 o; o.x = t0; o.y = t1; o.z = t2; o.w = t3;
                *(float4*)&out[(size_t)node * OUT + c0] = o;
            }
        }
    }
}

// ---------------- tf32 mma.sync GEMM (layers 2 & 3), optional half output ----
template <int K, int OUT, bool BIAS, bool RELU, bool HOUT>
__global__ __launch_bounds__(256) void k_mmagemm(
        const float* __restrict__ hext, int hs,
        const float* __restrict__ W,
        const float* __restrict__ b,
        float* __restrict__ oext, int ds) {
    const float* __restrict__ h = sel_src(hext, hs);
    float* __restrict__ out = HOUT ? nullptr : sel_dst(oext, ds);
    __half* __restrict__ hout = HOUT ? (__half*)g_hbuf : nullptr;
    constexpr int KC = 32;
    constexpr int NCH = K / KC;
    constexpr int AS = 40;
    constexpr int BS = OUT + 8;
    constexpr int NT = OUT / 8;
    __shared__ uint32_t Asm[128 * AS];
    __shared__ uint32_t Bsm[KC * BS];

    int tid = threadIdx.x;
    int wid = tid >> 5, lane = tid & 31;
    int g = lane >> 2, t4 = lane & 3;
    int tile0 = blockIdx.x * 128;

    float acc[NT][4];
#pragma unroll
    for (int nt = 0; nt < NT; nt++)
#pragma unroll
        for (int j = 0; j < 4; j++) acc[nt][j] = 0.f;

    for (int c = 0; c < NCH; c++) {
        int kc = c * KC;
        for (int i = tid; i < 128 * (KC / 4); i += 256) {
            int row = i >> 3, j = i & 7;
            int node = tile0 + row;
            float4 v = make_float4(0.f, 0.f, 0.f, 0.f);
            if (node < NN) v = *(const float4*)&h[(size_t)node * K + kc + 4 * j];
            uint4 t;
            t.x = f2tf32(v.x); t.y = f2tf32(v.y);
            t.z = f2tf32(v.z); t.w = f2tf32(v.w);
            *(uint4*)&Asm[row * AS + 4 * j] = t;
        }
        for (int i = tid; i < KC * (OUT / 4); i += 256) {
            int k = i / (OUT / 4), j = i % (OUT / 4);
            float4 v = *(const float4*)&W[(size_t)(kc + k) * OUT + 4 * j];
            uint4 t;
            t.x = f2tf32(v.x); t.y = f2tf32(v.y);
            t.z = f2tf32(v.z); t.w = f2tf32(v.w);
            *(uint4*)&Bsm[k * BS + 4 * j] = t;
        }
        __syncthreads();

#pragma unroll
        for (int ks = 0; ks < KC / 8; ks++) {
            int k0 = ks * 8;
            uint32_t a[4];
            const uint32_t* ar0 = &Asm[(wid * 16 + g) * AS + k0 + t4];
            const uint32_t* ar1 = &Asm[(wid * 16 + g + 8) * AS + k0 + t4];
            a[0] = ar0[0]; a[1] = ar1[0]; a[2] = ar0[4]; a[3] = ar1[4];
#pragma unroll
            for (int nt = 0; nt < NT; nt++) {
                uint32_t bb[2];
                bb[0] = Bsm[(k0 + t4) * BS + nt * 8 + g];
                bb[1] = Bsm[(k0 + t4 + 4) * BS + nt * 8 + g];
                mma_tf32_16n8k8(acc[nt], a, bb);
            }
        }
        __syncthreads();
    }

    int node0 = tile0 + wid * 16 + g;
    int node1 = node0 + 8;
#pragma unroll
    for (int nt = 0; nt < NT; nt++) {
        int col = nt * 8 + 2 * t4;
        float2 bv = make_float2(0.f, 0.f);
        if (BIAS) bv = *(const float2*)&b[col];
        float2 o0 = make_float2(acc[nt][0] + bv.x, acc[nt][1] + bv.y);
        float2 o1 = make_float2(acc[nt][2] + bv.x, acc[nt][3] + bv.y);
        if (RELU) {
            o0.x = fmaxf(o0.x, 0.f); o0.y = fmaxf(o0.y, 0.f);
            o1.x = fmaxf(o1.x, 0.f); o1.y = fmaxf(o1.y, 0.f);
        }
        if (HOUT) {
            if (node0 < NN)
                *(__half2*)&hout[(size_t)node0 * OUT + col] = __floats2half2_rn(o0.x, o0.y);
            if (node1 < NN)
                *(__half2*)&hout[(size_t)node1 * OUT + col] = __floats2half2_rn(o1.x, o1.y);
        } else {
            if (node0 < NN) *(float2*)&out[(size_t)node0 * OUT + col] = o0;
            if (node1 < NN) *(float2*)&out[(size_t)node1 * OUT + col] = o1;
        }
    }
}

// ---------------- launch ------------------------------------------------------
extern "C" void kernel_launch(void* const* d_in, const int* in_sizes, int n_in,
                              void* d_out, int out_size) {
    const float* x  = (const float*)d_in[0];
    const int* ei32 = (const int*)d_in[1];
    const float* W1 = (const float*)d_in[2];
    const float* b1 = (const float*)d_in[3];
    const float* W2 = (const float*)d_in[4];
    const float* b2 = (const float*)d_in[5];
    const float* W3 = (const float*)d_in[6];
    const float* b3 = (const float*)d_in[7];
    float* out      = (float*)d_out;
    int E = in_sizes[1] / 2;

    // CSR build
    k_init<<<(NN + 255) / 256, 256>>>(ei32);
    k_count<<<(E / 4 + 255) / 256, 256>>>(ei32, E);
    k_scan1<<<SCAN_NBLK, 256>>>();
    k_scan2<<<1, 128>>>();
    k_scan3<<<SCAN_NBLK, 256>>>();
    k_scatter<<<(E / 2 + 255) / 256, 256>>>(ei32, E);

    int agg16 = (NN * 16 + 255) / 256;
    int agg8  = (NN * 8 + 255) / 256;
    int gScalar = (NN + 31) / 32;
    int gMMA = (NN + 127) / 128;  // 782

    // layer 1: agg(x)[12] fp32 -> scalar GEMM 12->64 (+b1, relu) -> fp16 hbuf
    k_agg<12, 16, 1, false, false, false><<<agg16, 256>>>(x, 0, nullptr, 1, nullptr);
    k_gemm<12, 64, 12, true, true, true><<<gScalar, dim3(16, 8)>>>(nullptr, 1, W1, b1, nullptr, 0);

    // layer 2: agg[64] fp16-gather (GRP8/VEC8) -> buf1 -> tf32 GEMM 64->128 -> buf2
    k_agg<64, 8, 8, true, false, false><<<agg8, 256>>>(nullptr, 0, nullptr, 1, nullptr);
    k_mmagemm<64, 128, true, true, false><<<gMMA, 256>>>(nullptr, 1, W2, b2, nullptr, 2);

    // layer 3: tf32 GEMM 128->96 -> fp16 hbuf -> agg[96] fp16-gather (+b3) -> out
    k_mmagemm<128, 96, false, false, true><<<gMMA, 256>>>(nullptr, 2, W3, nullptr, nullptr, 0);
    k_agg<96, 16, 8, true, true, false><<<agg16, 256>>>(nullptr, 0, out, 0, b3);
}